// round 1
// baseline (speedup 1.0000x reference)
#include <cuda_runtime.h>
#include <math.h>

// Problem constants (fixed by the dataset): B=256, K=512, D=1024
#define B_SZ 256
#define K_SZ 512
#define D_SZ 1024
#define INV_T (1.0f / 0.07f)

#define K_PER_BLOCK 8                    // 8 warps per block, one k per warp
#define BLOCKS_PER_B (K_SZ / K_PER_BLOCK)  // 64
#define NBLK (B_SZ * BLOCKS_PER_B)         // 16384

// Scratch (no cudaMalloc allowed)
__device__ float g_img_n[B_SZ * D_SZ];   // normalized bg_img (1 MiB)
__device__ float g_fg_per_b[B_SZ];       // exp(fg_logit / T) per sample
__device__ float g_part[NBLK];           // per-block partial sums of exp(bg_logit/T)

// ---------------------------------------------------------------------------
// Kernel 1: per-row L2 norm of bg_img + fg dot, fused in one float4 pass.
// grid = B, block = 256 (each thread owns one float4 of the 1024-float row)
// ---------------------------------------------------------------------------
__global__ void __launch_bounds__(256) norm_fg_kernel(
    const float* __restrict__ img, const float* __restrict__ fg)
{
    const int b = blockIdx.x;
    const int t = threadIdx.x;

    const float4* img4 = (const float4*)(img + (size_t)b * D_SZ);
    const float4* fg4  = (const float4*)(fg  + (size_t)b * D_SZ);

    float4 v = img4[t];
    float4 f = fg4[t];

    float ss = v.x * v.x + v.y * v.y + v.z * v.z + v.w * v.w;
    float fd = v.x * f.x + v.y * f.y + v.z * f.z + v.w * f.w;

    __shared__ float s_ss[8];
    __shared__ float s_fd[8];

    #pragma unroll
    for (int o = 16; o > 0; o >>= 1) {
        ss += __shfl_xor_sync(0xFFFFFFFFu, ss, o);
        fd += __shfl_xor_sync(0xFFFFFFFFu, fd, o);
    }
    const int w = t >> 5, l = t & 31;
    if (l == 0) { s_ss[w] = ss; s_fd[w] = fd; }
    __syncthreads();

    __shared__ float s_inv;
    __shared__ float s_fdot;
    if (t == 0) {
        float tss = 0.f, tfd = 0.f;
        #pragma unroll
        for (int i = 0; i < 8; i++) { tss += s_ss[i]; tfd += s_fd[i]; }
        s_inv  = 1.0f / sqrtf(tss);
        s_fdot = tfd;
    }
    __syncthreads();

    const float inv = s_inv;
    float4 o = make_float4(v.x * inv, v.y * inv, v.z * inv, v.w * inv);
    ((float4*)(g_img_n + (size_t)b * D_SZ))[t] = o;

    if (t == 0) {
        g_fg_per_b[b] = expf(s_fdot * inv * INV_T);
    }
}

// ---------------------------------------------------------------------------
// Kernel 2: the HBM streamer. One warp computes one (b,k) dot over D=1024.
// Each lane: 8 independent float4 loads per operand (front-batched -> MLP).
// img row is L2/L1 resident (reused by 512 warps per b).
// grid = 16384, block = 256 (8 warps)
// ---------------------------------------------------------------------------
__global__ void __launch_bounds__(256) logits_kernel(const float* __restrict__ pro)
{
    const int blk   = blockIdx.x;
    const int b     = blk / BLOCKS_PER_B;
    const int kbase = (blk % BLOCKS_PER_B) * K_PER_BLOCK;
    const int w     = threadIdx.x >> 5;
    const int l     = threadIdx.x & 31;
    const int k     = kbase + w;

    const float4* p4 = (const float4*)(pro + ((size_t)b * K_SZ + k) * D_SZ);
    const float4* i4 = (const float4*)(g_img_n + (size_t)b * D_SZ);

    float acc = 0.f;
    #pragma unroll
    for (int j = 0; j < 8; j++) {
        float4 a = i4[j * 32 + l];
        float4 c = p4[j * 32 + l];
        acc += a.x * c.x + a.y * c.y + a.z * c.z + a.w * c.w;
    }

    #pragma unroll
    for (int o = 16; o > 0; o >>= 1)
        acc += __shfl_xor_sync(0xFFFFFFFFu, acc, o);

    __shared__ float s[K_PER_BLOCK];
    if (l == 0) s[w] = expf(acc * INV_T);
    __syncthreads();

    if (threadIdx.x == 0) {
        float tsum = 0.f;
        #pragma unroll
        for (int i = 0; i < K_PER_BLOCK; i++) tsum += s[i];
        g_part[blk] = tsum;   // fixed order: deterministic across replays
    }
}

// ---------------------------------------------------------------------------
// Kernel 3: deterministic final reduce in double; writes the scalar loss.
// grid = 1, block = 256
// ---------------------------------------------------------------------------
__global__ void __launch_bounds__(256) reduce_kernel(float* __restrict__ out)
{
    const int t = threadIdx.x;

    double acc = 0.0;
    for (int i = t; i < NBLK; i += 256) acc += (double)g_part[i];
    double fg = (double)g_fg_per_b[t];

    __shared__ double sa[256];
    __shared__ double sf[256];
    sa[t] = acc;
    sf[t] = fg;
    __syncthreads();

    #pragma unroll
    for (int s = 128; s > 0; s >>= 1) {
        if (t < s) { sa[t] += sa[t + s]; sf[t] += sf[t + s]; }
        __syncthreads();
    }

    if (t == 0) {
        double pos = sa[0] / (double)K_SZ;   // sum_b mean_k exp(...)
        double neg = pos + sf[0];
        out[0] = (float)(-log(pos / neg));
    }
}

// ---------------------------------------------------------------------------
extern "C" void kernel_launch(void* const* d_in, const int* in_sizes, int n_in,
                              void* d_out, int out_size)
{
    const float* img = (const float*)d_in[0];  // bg_img_feature [256,1024]
    const float* fg  = (const float*)d_in[1];  // fg_pro_feature [256,1024]
    const float* pro = (const float*)d_in[2];  // bg_pro_feature [256,512,1024]

    norm_fg_kernel<<<B_SZ, 256>>>(img, fg);
    logits_kernel<<<NBLK, 256>>>(pro);
    reduce_kernel<<<1, 256>>>((float*)d_out);
}

// round 2
// speedup vs baseline: 1.0836x; 1.0836x over previous
#include <cuda_runtime.h>
#include <math.h>

// Problem constants (fixed by the dataset): B=256, K=512, D=1024
#define B_SZ 256
#define K_SZ 512
#define D_SZ 1024
#define INV_T (1.0f / 0.07f)

#define K_PER_BLOCK 8                      // 8 warps per block, one k per warp
#define BLOCKS_PER_B (K_SZ / K_PER_BLOCK)  // 64
#define NBLK (B_SZ * BLOCKS_PER_B)         // 16384

// Scratch (no cudaMalloc allowed)
__device__ float g_fg_per_b[B_SZ];       // exp(fg_logit / T) per sample
__device__ float g_part[NBLK];           // per-block partial sums of exp(bg_logit/T)

// ---------------------------------------------------------------------------
// Fused kernel: per-block img-row normalization (redundant 64x per row, L2
// hits) + 8 warps each streaming one pro row from DRAM and dotting against
// the smem-resident img row. kgrp==0 blocks additionally compute the fg dot.
// grid = 16384, block = 256 (8 warps)
// ---------------------------------------------------------------------------
__global__ void __launch_bounds__(256) fused_kernel(
    const float* __restrict__ img,
    const float* __restrict__ fg,
    const float* __restrict__ pro)
{
    __shared__ float4 s_img[256];   // 4 KB: the img row, float4 per thread
    __shared__ float  s_ss[8];
    __shared__ float  s_fg[8];
    __shared__ float  s_part[8];

    const int blk  = blockIdx.x;
    const int b    = blk >> 6;          // blk / BLOCKS_PER_B
    const int kgrp = blk & 63;          // blk % BLOCKS_PER_B
    const int t    = threadIdx.x;
    const int w    = t >> 5;
    const int l    = t & 31;

    // ---- load img row into smem + sum of squares ----
    float4 v = ((const float4*)(img + (size_t)b * D_SZ))[t];
    s_img[t] = v;

    float ss = v.x * v.x + v.y * v.y + v.z * v.z + v.w * v.w;
    #pragma unroll
    for (int o = 16; o > 0; o >>= 1)
        ss += __shfl_xor_sync(0xFFFFFFFFu, ss, o);
    if (l == 0) s_ss[w] = ss;
    __syncthreads();

    float tss = 0.f;
    #pragma unroll
    for (int i = 0; i < 8; i++) tss += s_ss[i];
    const float inv = 1.0f / sqrtf(tss);

    // ---- fg dot: only in the first block of each sample (256 blocks) ----
    if (kgrp == 0) {
        float4 f = ((const float4*)(fg + (size_t)b * D_SZ))[t];
        float fd = v.x * f.x + v.y * f.y + v.z * f.z + v.w * f.w;
        #pragma unroll
        for (int o = 16; o > 0; o >>= 1)
            fd += __shfl_xor_sync(0xFFFFFFFFu, fd, o);
        if (l == 0) s_fg[w] = fd;
        __syncthreads();
        if (t == 0) {
            float tfd = 0.f;
            #pragma unroll
            for (int i = 0; i < 8; i++) tfd += s_fg[i];
            g_fg_per_b[b] = expf(tfd * inv * INV_T);
        }
    }

    // ---- each warp: one (b,k) dot, pro streamed from DRAM ----
    const int k = (kgrp << 3) + w;
    const float4* p4 = (const float4*)(pro + ((size_t)b * K_SZ + k) * D_SZ);

    // front-batch the 8 independent streaming loads for max MLP
    float4 p[8];
    #pragma unroll
    for (int j = 0; j < 8; j++)
        p[j] = __ldcs(p4 + j * 32 + l);

    float acc = 0.f;
    #pragma unroll
    for (int j = 0; j < 8; j++) {
        float4 a = s_img[j * 32 + l];
        acc += a.x * p[j].x + a.y * p[j].y + a.z * p[j].z + a.w * p[j].w;
    }

    #pragma unroll
    for (int o = 16; o > 0; o >>= 1)
        acc += __shfl_xor_sync(0xFFFFFFFFu, acc, o);
    if (l == 0) s_part[w] = expf(acc * inv * INV_T);
    __syncthreads();

    if (t == 0) {
        float tsum = 0.f;
        #pragma unroll
        for (int i = 0; i < 8; i++) tsum += s_part[i];
        g_part[blk] = tsum;   // fixed order: deterministic across replays
    }
}

// ---------------------------------------------------------------------------
// Final deterministic reduce in double; writes the scalar loss.
// grid = 1, block = 256
// ---------------------------------------------------------------------------
__global__ void __launch_bounds__(256) reduce_kernel(float* __restrict__ out)
{
    const int t = threadIdx.x;

    double acc = 0.0;
    for (int i = t; i < NBLK; i += 256) acc += (double)g_part[i];
    double fgv = (double)g_fg_per_b[t];

    __shared__ double sa[256];
    __shared__ double sf[256];
    sa[t] = acc;
    sf[t] = fgv;
    __syncthreads();

    #pragma unroll
    for (int s = 128; s > 0; s >>= 1) {
        if (t < s) { sa[t] += sa[t + s]; sf[t] += sf[t + s]; }
        __syncthreads();
    }

    if (t == 0) {
        double pos = sa[0] / (double)K_SZ;   // sum_b mean_k exp(...)
        double neg = pos + sf[0];
        out[0] = (float)(-log(pos / neg));
    }
}

// ---------------------------------------------------------------------------
extern "C" void kernel_launch(void* const* d_in, const int* in_sizes, int n_in,
                              void* d_out, int out_size)
{
    const float* img = (const float*)d_in[0];  // bg_img_feature [256,1024]
    const float* fg  = (const float*)d_in[1];  // fg_pro_feature [256,1024]
    const float* pro = (const float*)d_in[2];  // bg_pro_feature [256,512,1024]

    fused_kernel<<<NBLK, 256>>>(img, fg, pro);
    reduce_kernel<<<1, 256>>>((float*)d_out);
}